// round 10
// baseline (speedup 1.0000x reference)
#include <cuda_runtime.h>
#include <cuda_bf16.h>
#include <math.h>
#include <stdint.h>

#define Bb    512
#define Tt    32
#define DEPTH 512
#define RNN   512
#define NCC   128
#define G4    2048
#define BT    16384
#define BRNN  (Bb*RNN)
#define SMEM_1B 99328   // 1KB align slack + 96KB single chunk buffer

// ---------------- device scratch -------------------------------------------
// Row order: R = t*512 + b. Gate cols interleaved: n' = r*4 + g.
__device__ float g_Z[BT * G4];
__device__ float g_hall[(Tt + 1) * BRNN];
__device__ float g_c0[BRNN];
__device__ float g_c1[BRNN];
__device__ float g_part[2 * Bb * G4];
__device__ __align__(16) unsigned short g_Xs[3 * 128 * 10 * 8192];
__device__ __align__(16) unsigned short g_Ws[3 * 16 * 10 * 8192];
__device__ __align__(16) unsigned short g_Rs[3 * 16 * 8 * 8192];
__device__ __align__(16) unsigned short g_hs[3 * 4 * 8 * 8192];

// ---------------- PTX helpers ----------------------------------------------
static __device__ __forceinline__ uint32_t s2u(const void* p) {
    uint32_t a;
    asm("{ .reg .u64 t; cvta.to.shared.u64 t, %1; cvt.u32.u64 %0, t; }" : "=r"(a) : "l"(p));
    return a;
}
static __device__ __forceinline__ void cp16(uint32_t d, const void* s) {
    asm volatile("cp.async.cg.shared.global [%0], [%1], 16;" :: "r"(d), "l"(s));
}
#define CP_COMMIT() asm volatile("cp.async.commit_group;" ::: "memory")
#define CP_WAIT(n)  asm volatile("cp.async.wait_group %0;" :: "n"(n) : "memory")

static __device__ __forceinline__ void ldsm4(uint32_t* r, uint32_t a) {
    asm volatile("ldmatrix.sync.aligned.m8n8.x4.shared.b16 {%0,%1,%2,%3}, [%4];"
        : "=r"(r[0]), "=r"(r[1]), "=r"(r[2]), "=r"(r[3]) : "r"(a));
}
static __device__ __forceinline__ void ldsm2(uint32_t* r, uint32_t a) {
    asm volatile("ldmatrix.sync.aligned.m8n8.x2.shared.b16 {%0,%1}, [%2];"
        : "=r"(r[0]), "=r"(r[1]) : "r"(a));
}
static __device__ __forceinline__ void mma16816(float* d, const uint32_t* a, const uint32_t* b) {
    asm volatile("mma.sync.aligned.m16n8k16.row.col.f32.bf16.bf16.f32 "
        "{%0,%1,%2,%3}, {%4,%5,%6,%7}, {%8,%9}, {%0,%1,%2,%3};"
        : "+f"(d[0]), "+f"(d[1]), "+f"(d[2]), "+f"(d[3])
        : "r"(a[0]), "r"(a[1]), "r"(a[2]), "r"(a[3]), "r"(b[0]), "r"(b[1]));
}

// ---------------- split helpers --------------------------------------------
static __device__ __forceinline__ void split3(float x, unsigned short& s1,
                                              unsigned short& s2, unsigned short& s3) {
    __nv_bfloat16 b1 = __float2bfloat16_rn(x);
    float r1 = x - __bfloat162float(b1);
    __nv_bfloat16 b2 = __float2bfloat16_rn(r1);
    float r2 = r1 - __bfloat162float(b2);
    __nv_bfloat16 b3 = __float2bfloat16_rn(r2);
    s1 = __bfloat16_as_ushort(b1); s2 = __bfloat16_as_ushort(b2); s3 = __bfloat16_as_ushort(b3);
}
static __device__ __forceinline__ uint32_t swz(uint32_t o) { return o ^ ((o >> 3) & 0x70); }
static __device__ __forceinline__ void put_split4(char* base, int s_mul, int mt, int nch,
                                                  int c, int rb, int kk, float4 v) {
    uint32_t sw = swz(((uint32_t)(rb >> 3) << 10) + ((uint32_t)(rb & 7) << 7) + ((uint32_t)kk << 1));
    float xs[4] = {v.x, v.y, v.z, v.w};
    unsigned short a[3][4];
    #pragma unroll
    for (int i = 0; i < 4; i++) split3(xs[i], a[0][i], a[1][i], a[2][i]);
    #pragma unroll
    for (int s = 0; s < 3; s++) {
        ushort4 o = make_ushort4(a[s][0], a[s][1], a[s][2], a[s][3]);
        *(ushort4*)(base + ((size_t)(s * s_mul + mt) * nch + c) * 16384 + sw) = o;
    }
}
__device__ __forceinline__ float sigm(float x) { return 1.f / (1.f + expf(-x)); }

// ---------------- prep kernels ----------------------------------------------
__global__ void assemble_splitX_kernel(const float* __restrict__ f_pool,
                                       const float* __restrict__ gt) {
    int idx = blockIdx.x * blockDim.x + threadIdx.x;
    if (idx >= BT * 160) return;
    int R = idx / 160, k0 = (idx - R * 160) * 4;
    int t = R >> 9, b = R & 511;
    float4 v;
    if (k0 < DEPTH) v = *(const float4*)(f_pool + ((size_t)b * Tt + t) * DEPTH + k0);
    else {
        v = (t == 0) ? make_float4(0.f, 0.f, 0.f, 0.f)
                     : *(const float4*)(gt + ((size_t)b * Tt + t - 1) * NCC + (k0 - DEPTH));
    }
    put_split4((char*)g_Xs, 128, R >> 7, 10, k0 >> 6, R & 127, k0 & 63, v);
}

__global__ void split_W_kernel(const float* __restrict__ W) {
    int idx = blockIdx.x * blockDim.x + threadIdx.x;
    if (idx >= 160 * 2048) return;
    int kc = idx >> 11, n = idx & 2047, k0 = kc * 4;
    int g = n >> 9, r = n & 511, np = r * 4 + g;
    float4 v;
    v.x = W[(size_t)(k0 + 0) * G4 + n]; v.y = W[(size_t)(k0 + 1) * G4 + n];
    v.z = W[(size_t)(k0 + 2) * G4 + n]; v.w = W[(size_t)(k0 + 3) * G4 + n];
    put_split4((char*)g_Ws, 16, np >> 7, 10, k0 >> 6, np & 127, k0 & 63, v);
}

__global__ void split_rec_kernel(const float* __restrict__ rec) {
    int idx = blockIdx.x * blockDim.x + threadIdx.x;
    if (idx >= 128 * 2048) return;
    int kc = idx >> 11, n = idx & 2047, k0 = kc * 4;
    int g = n >> 9, r = n & 511, np = r * 4 + g;
    float4 v;
    v.x = rec[(size_t)(k0 + 0) * G4 + n]; v.y = rec[(size_t)(k0 + 1) * G4 + n];
    v.z = rec[(size_t)(k0 + 2) * G4 + n]; v.w = rec[(size_t)(k0 + 3) * G4 + n];
    put_split4((char*)g_Rs, 16, np >> 7, 8, k0 >> 6, np & 127, k0 & 63, v);
}

// ============ shared GEMM body: single 96KB buffer, 2 CTAs/SM ===============
// tile 128x128, 8 warps (warp tile 64x32), 6 split products, chunks of K=64.
template <int NCH_STRIDE>
static __device__ __forceinline__ void gemm_body(
    const char* A8, const char* B8, int mt, int nt, int amt_stride,
    int c0, int c1, float acc[4][4][4], char* dsm, int tid, int lane, int wid) {
    const int wm = wid & 1, wn = wid >> 1;
    uint32_t sb = (s2u(dsm) + 1023u) & ~1023u;

    const int l7 = lane & 7;
    const uint32_t xm = (uint32_t)l7 << 4;
    const int asub = lane >> 3;
    const uint32_t akoff = (uint32_t)(asub >> 1) * 16;
    const uint32_t bkoff = (uint32_t)((lane >> 3) & 1) * 16;
    uint32_t arb[4], brb[4];
    #pragma unroll
    for (int m4 = 0; m4 < 4; m4++) {
        int row = wm * 64 + m4 * 16 + (asub & 1) * 8 + l7;
        arb[m4] = (uint32_t)(row >> 3) * 1024u + (uint32_t)l7 * 128u;
    }
    #pragma unroll
    for (int n4 = 0; n4 < 4; n4++) {
        int row = wn * 32 + n4 * 8 + l7;
        brb[n4] = (uint32_t)(row >> 3) * 1024u + (uint32_t)l7 * 128u + 49152u;  // B region base
    }

    for (int c = c0; c < c1; c++) {
        if (c != c0) __syncthreads();          // buffer reuse guard
        #pragma unroll
        for (int tau = 0; tau < 6; tau++) {    // load 6 x 16KB sub-tiles
            const char* g = (tau < 3)
                ? A8 + ((size_t)(tau * amt_stride + mt) * NCH_STRIDE + c) * 16384
                : B8 + ((size_t)((tau - 3) * 16 + nt) * NCH_STRIDE + c) * 16384;
            uint32_t sdst = sb + (uint32_t)tau * 16384u + (uint32_t)tid * 16u;
            const char* gs = g + tid * 16;
            #pragma unroll
            for (int u = 0; u < 4; u++) cp16(sdst + u * 4096u, gs + u * 4096);
        }
        CP_COMMIT(); CP_WAIT(0);
        __syncthreads();
        #pragma unroll
        for (int ks = 0; ks < 4; ks++) {
            uint32_t kb = (uint32_t)ks * 32;
            #pragma unroll
            for (int i = 0; i < 3; i++) {      // a-split outer (low reg pressure)
                uint32_t a4[4][4];
                uint32_t ab = sb + (uint32_t)i * 16384u + ((kb + akoff) ^ xm);
                #pragma unroll
                for (int m4 = 0; m4 < 4; m4++) ldsm4(a4[m4], ab + arb[m4]);
                #pragma unroll
                for (int j = 0; j + i < 3; j++) {
                    uint32_t b2[4][2];
                    // NOTE: B region offset lives ONLY in brb (round-9 bug: it was added twice)
                    uint32_t bbq = sb + (uint32_t)j * 16384u + ((kb + bkoff) ^ xm);
                    #pragma unroll
                    for (int n4 = 0; n4 < 4; n4++) ldsm2(b2[n4], bbq + brb[n4]);
                    #pragma unroll
                    for (int m4 = 0; m4 < 4; m4++)
                        #pragma unroll
                        for (int n4 = 0; n4 < 4; n4++)
                            mma16816(acc[m4][n4], a4[m4], b2[n4]);
                }
            }
        }
    }
}

// Z slab: rows [mt0*128, mt0*128+1024) = 2 time steps. grid(16 nt, 8 mt).
__global__ __launch_bounds__(256, 2) void hmma_Z_slab_kernel(int mt0, const float* __restrict__ bias) {
    extern __shared__ char dsm[];
    const int tid = threadIdx.x, lane = tid & 31, wid = tid >> 5;
    const int mt = mt0 + blockIdx.y, nt = blockIdx.x;
    const int wm = wid & 1, wn = wid >> 1;
    float acc[4][4][4];
    #pragma unroll
    for (int m4 = 0; m4 < 4; m4++)
        #pragma unroll
        for (int n4 = 0; n4 < 4; n4++)
            #pragma unroll
            for (int e = 0; e < 4; e++) acc[m4][n4][e] = 0.f;

    gemm_body<10>((const char*)g_Xs, (const char*)g_Ws, mt, nt, 128, 0, 10,
                  acc, dsm, tid, lane, wid);

    #pragma unroll
    for (int m4 = 0; m4 < 4; m4++) {
        int grow = mt * 128 + wm * 64 + m4 * 16 + (lane >> 2);
        #pragma unroll
        for (int n4 = 0; n4 < 4; n4++) {
            int gcol = nt * 128 + wn * 32 + n4 * 8 + (lane & 3) * 2;
            float b0 = bias[(gcol & 3) * 512 + (gcol >> 2)];
            float b1 = bias[((gcol + 1) & 3) * 512 + ((gcol + 1) >> 2)];
            float2 v;
            v.x = acc[m4][n4][0] + b0; v.y = acc[m4][n4][1] + b1;
            *(float2*)(g_Z + (size_t)grow * G4 + gcol) = v;
            v.x = acc[m4][n4][2] + b0; v.y = acc[m4][n4][3] + b1;
            *(float2*)(g_Z + (size_t)(grow + 8) * G4 + gcol) = v;
        }
    }
}

// step GEMM: g_part[kz] = h @ rec, split-K=2. grid(16 nt, 4 mt, 2 kz).
__global__ __launch_bounds__(256, 2) void hmma_step_kernel() {
    extern __shared__ char dsm[];
    const int tid = threadIdx.x, lane = tid & 31, wid = tid >> 5;
    const int mt = blockIdx.y, nt = blockIdx.x, kz = blockIdx.z;
    const int wm = wid & 1, wn = wid >> 1;
    float* out = g_part + (size_t)kz * (Bb * G4);
    float acc[4][4][4];
    #pragma unroll
    for (int m4 = 0; m4 < 4; m4++)
        #pragma unroll
        for (int n4 = 0; n4 < 4; n4++)
            #pragma unroll
            for (int e = 0; e < 4; e++) acc[m4][n4][e] = 0.f;

    gemm_body<8>((const char*)g_hs, (const char*)g_Rs, mt, nt, 4, kz * 4, kz * 4 + 4,
                 acc, dsm, tid, lane, wid);

    #pragma unroll
    for (int m4 = 0; m4 < 4; m4++) {
        int grow = mt * 128 + wm * 64 + m4 * 16 + (lane >> 2);
        #pragma unroll
        for (int n4 = 0; n4 < 4; n4++) {
            int gcol = nt * 128 + wn * 32 + n4 * 8 + (lane & 3) * 2;
            float2 v;
            v.x = acc[m4][n4][0]; v.y = acc[m4][n4][1];
            *(float2*)(out + (size_t)grow * G4 + gcol) = v;
            v.x = acc[m4][n4][2]; v.y = acc[m4][n4][3];
            *(float2*)(out + (size_t)(grow + 8) * G4 + gcol) = v;
        }
    }
}

// ---------------- gate: Z(+parts) + c -> h, c, h-splits ---------------------
__global__ __launch_bounds__(256) void gate_kernel(int t) {
    int idx = blockIdx.x * blockDim.x + threadIdx.x;
    if (idx >= Bb * 128) return;
    int r4 = (idx & 127) * 4, b = idx >> 7;
    const float* __restrict__ c_prev = (t & 1) ? g_c1 : g_c0;
    float* __restrict__ c_out = (t & 1) ? g_c0 : g_c1;
    float* __restrict__ h_out = g_hall + (size_t)(t + 1) * BRNN;

    const float* zb = g_Z + ((size_t)(t * Bb + b)) * G4 + r4 * 4;
    const float* p0 = g_part + (size_t)b * G4 + r4 * 4;
    const float* p1 = p0 + (size_t)Bb * G4;
    float4 cp = (t == 0) ? make_float4(0.f, 0.f, 0.f, 0.f)
                         : *(const float4*)(c_prev + (size_t)b * RNN + r4);
    float cpv[4] = {cp.x, cp.y, cp.z, cp.w};
    float4 cv, hv;
    float* cvp = &cv.x; float* hvp = &hv.x;
    #pragma unroll
    for (int u = 0; u < 4; u++) {
        float4 z = *(const float4*)(zb + u * 4);
        if (t > 0) {
            float4 p = *(const float4*)(p0 + u * 4);
            float4 q = *(const float4*)(p1 + u * 4);
            z.x += p.x + q.x; z.y += p.y + q.y; z.z += p.z + q.z; z.w += p.w + q.w;
        }
        float c2 = sigm(z.y) * cpv[u] + sigm(z.x) * tanhf(z.z);
        float h2 = sigm(z.w) * tanhf(c2);
        cvp[u] = c2; hvp[u] = h2;
    }
    *(float4*)(c_out + (size_t)b * RNN + r4) = cv;
    *(float4*)(h_out + (size_t)b * RNN + r4) = hv;
    put_split4((char*)g_hs, 4, b >> 7, 8, r4 >> 6, b & 127, r4 & 63, hv);
}

// ---------------- logits slice: 8 CTAs per time step ------------------------
__global__ __launch_bounds__(256) void logits_argmax_kernel(
    int by0, const float* __restrict__ sw_, const float* __restrict__ sb_,
    float* __restrict__ out) {
    __shared__ float As[2][8][68];
    __shared__ float Bs[2][8][128];
    const int by = by0 + blockIdx.x, tid = threadIdx.x;
    const int tx = tid & 15, ty = tid >> 4;
    const int la_r = tid >> 2, la_k = (tid & 3) * 2;
    const int lb_k = tid >> 5, lb_j = (tid & 31) * 4;
    const float* Aptr = g_hall + BRNN + (size_t)(by * 64 + la_r) * RNN + la_k;
    const float* Bptr = sw_ + (size_t)lb_k * NCC + lb_j;

    float acc[4][8];
    #pragma unroll
    for (int i = 0; i < 4; i++)
        #pragma unroll
        for (int j = 0; j < 8; j++) acc[i][j] = 0.f;

    float2 aN = *(const float2*)(Aptr);
    float4 bN = *(const float4*)(Bptr);
    int buf = 0;
    for (int k0 = 0; k0 < RNN; k0 += 8) {
        As[buf][la_k + 0][la_r] = aN.x; As[buf][la_k + 1][la_r] = aN.y;
        *(float4*)&Bs[buf][lb_k][lb_j] = bN;
        if (k0 + 8 < RNN) {
            aN = *(const float2*)(Aptr + k0 + 8);
            bN = *(const float4*)(Bptr + (size_t)(k0 + 8) * NCC);
        }
        __syncthreads();
        #pragma unroll
        for (int kk = 0; kk < 8; kk++) {
            float av[4], bv[8];
            #pragma unroll
            for (int i = 0; i < 4; i++) av[i] = As[buf][kk][ty * 4 + i];
            #pragma unroll
            for (int j = 0; j < 8; j++) bv[j] = Bs[buf][kk][tx * 8 + j];
            #pragma unroll
            for (int i = 0; i < 4; i++)
                #pragma unroll
                for (int j = 0; j < 8; j++) acc[i][j] += av[i] * bv[j];
        }
        buf ^= 1;
    }
    #pragma unroll
    for (int i = 0; i < 4; i++) {
        float best = -1e30f; int bidx = 0;
        #pragma unroll
        for (int j = 0; j < 8; j++) {
            float v = acc[i][j] + sb_[tx * 8 + j];
            if (v > best) { best = v; bidx = tx * 8 + j; }
        }
        #pragma unroll
        for (int off = 8; off >= 1; off >>= 1) {
            float ob = __shfl_xor_sync(0xffffffffu, best, off);
            int oi = __shfl_xor_sync(0xffffffffu, bidx, off);
            if (ob > best || (ob == best && oi < bidx)) { best = ob; bidx = oi; }
        }
        int R = by * 64 + ty * 4 + i;     // R = t*512 + b
        int t = R >> 9, b = R & 511;
        float* orow = out + (size_t)b * (Tt * NCC) + t * NCC;
        #pragma unroll
        for (int j = 0; j < 8; j++) { int col = tx * 8 + j; orow[col] = (col == bidx) ? 1.f : 0.f; }
    }
}

__global__ void copy_final_kernel(float* __restrict__ out) {
    int i = blockIdx.x * blockDim.x + threadIdx.x;
    if (i < BRNN) {
        out[BT * NCC + i] = g_hall[(size_t)Tt * BRNN + i];
        out[BT * NCC + BRNN + i] = g_c0[i];   // t=31 odd -> wrote g_c0
    }
}

// ---------------- launch -----------------------------------------------------
extern "C" void kernel_launch(void* const* d_in, const int* in_sizes, int n_in,
                              void* d_out, int out_size) {
    const float* f_pool = (const float*)d_in[0];
    const float* gt     = (const float*)d_in[1];
    const float* W      = (const float*)d_in[2];
    const float* rec    = (const float*)d_in[3];
    const float* bias   = (const float*)d_in[4];
    const float* sw_    = (const float*)d_in[5];
    const float* sb_    = (const float*)d_in[6];
    float* out = (float*)d_out;

    static cudaStream_t s1 = nullptr, s2 = nullptr;
    static cudaEvent_t evFork = nullptr, evLog = nullptr;
    static cudaEvent_t evZ[16], evGate[32];
    if (!s1) {
        cudaStreamCreateWithFlags(&s1, cudaStreamNonBlocking);
        cudaStreamCreateWithFlags(&s2, cudaStreamNonBlocking);
        cudaEventCreateWithFlags(&evFork, cudaEventDisableTiming);
        cudaEventCreateWithFlags(&evLog, cudaEventDisableTiming);
        for (int s = 0; s < 16; s++) cudaEventCreateWithFlags(&evZ[s], cudaEventDisableTiming);
        for (int s = 0; s < 32; s++) cudaEventCreateWithFlags(&evGate[s], cudaEventDisableTiming);
        cudaFuncSetAttribute(hmma_Z_slab_kernel, cudaFuncAttributeMaxDynamicSharedMemorySize, SMEM_1B);
        cudaFuncSetAttribute(hmma_step_kernel, cudaFuncAttributeMaxDynamicSharedMemorySize, SMEM_1B);
    }

    assemble_splitX_kernel<<<(BT * 160 + 255) / 256, 256>>>(f_pool, gt);
    split_W_kernel<<<(160 * 2048 + 255) / 256, 256>>>(W);
    split_rec_kernel<<<(128 * 2048 + 255) / 256, 256>>>(rec);

    // fork Z slabs (2 t-steps each) onto s1
    cudaEventRecord(evFork, 0);
    cudaStreamWaitEvent(s1, evFork, 0);
    for (int s = 0; s < 16; s++) {
        hmma_Z_slab_kernel<<<dim3(16, 8), 256, SMEM_1B, s1>>>(8 * s, bias);
        cudaEventRecord(evZ[s], s1);
    }

    const int gate_blocks = (Bb * 128 + 255) / 256;
    for (int t = 0; t < Tt; t++) {
        if (t > 0)
            hmma_step_kernel<<<dim3(16, 4, 2), 256, SMEM_1B>>>();
        if ((t & 1) == 0) cudaStreamWaitEvent(0, evZ[t >> 1], 0);
        gate_kernel<<<gate_blocks, 256>>>(t);
        cudaEventRecord(evGate[t], 0);
        cudaStreamWaitEvent(s2, evGate[t], 0);
        logits_argmax_kernel<<<8, 256, 0, s2>>>(t * 8, sw_, sb_, out);
    }

    // join forked streams back into stream 0
    cudaEventRecord(evLog, s2);
    cudaStreamWaitEvent(0, evLog, 0);
    cudaStreamWaitEvent(0, evZ[15], 0);

    copy_final_kernel<<<(BRNN + 255) / 256, 256>>>(out);
}

// round 12
// speedup vs baseline: 1.3651x; 1.3651x over previous
#include <cuda_runtime.h>
#include <cuda_bf16.h>
#include <math.h>
#include <stdint.h>

#define Bb    512
#define Tt    32
#define DEPTH 512
#define RNN   512
#define NCC   128
#define G4    2048
#define BT    16384
#define BRNN  (Bb*RNN)
#define SMEM_DYN 197632   // 1KB align slack + 2 x 96KB chunk buffers

// ---------------- device scratch -------------------------------------------
// X/Z rows: r = b*32 + t. Archive rows: R = t*512 + b. Gate cols: n' = r*4+g (W/rec only).
__device__ float g_Z[BT * G4];
__device__ float g_hall[(Tt + 1) * BRNN];
__device__ float g_c0[BRNN];
__device__ float g_c1[BRNN];
__device__ float g_part[2 * Bb * G4];
__device__ __align__(16) unsigned short g_Xs[3 * 128 * 10 * 8192]; // X splits
__device__ __align__(16) unsigned short g_Ws[3 * 16 * 10 * 8192];  // kernel splits
__device__ __align__(16) unsigned short g_Rs[3 * 16 * 8 * 8192];   // rec splits
__device__ __align__(16) unsigned short g_hL[3 * 128 * 8 * 8192];  // h archive splits (R=t*512+b)
__device__ __align__(16) unsigned short g_Ss[3 * 8 * 8192];        // softmax_w splits

// ---------------- PTX helpers ----------------------------------------------
static __device__ __forceinline__ uint32_t s2u(const void* p) {
    uint32_t a;
    asm("{ .reg .u64 t; cvta.to.shared.u64 t, %1; cvt.u32.u64 %0, t; }" : "=r"(a) : "l"(p));
    return a;
}
static __device__ __forceinline__ void cp16(uint32_t d, const void* s) {
    asm volatile("cp.async.cg.shared.global [%0], [%1], 16;" :: "r"(d), "l"(s));
}
#define CP_COMMIT() asm volatile("cp.async.commit_group;" ::: "memory")
#define CP_WAIT(n)  asm volatile("cp.async.wait_group %0;" :: "n"(n) : "memory")

static __device__ __forceinline__ void ldsm4(uint32_t* r, uint32_t a) {
    asm volatile("ldmatrix.sync.aligned.m8n8.x4.shared.b16 {%0,%1,%2,%3}, [%4];"
        : "=r"(r[0]), "=r"(r[1]), "=r"(r[2]), "=r"(r[3]) : "r"(a));
}
static __device__ __forceinline__ void ldsm2(uint32_t* r, uint32_t a) {
    asm volatile("ldmatrix.sync.aligned.m8n8.x2.shared.b16 {%0,%1}, [%2];"
        : "=r"(r[0]), "=r"(r[1]) : "r"(a));
}
static __device__ __forceinline__ void mma16816(float* d, const uint32_t* a, const uint32_t* b) {
    asm volatile("mma.sync.aligned.m16n8k16.row.col.f32.bf16.bf16.f32 "
        "{%0,%1,%2,%3}, {%4,%5,%6,%7}, {%8,%9}, {%0,%1,%2,%3};"
        : "+f"(d[0]), "+f"(d[1]), "+f"(d[2]), "+f"(d[3])
        : "r"(a[0]), "r"(a[1]), "r"(a[2]), "r"(a[3]), "r"(b[0]), "r"(b[1]));
}

// ---------------- split helpers --------------------------------------------
static __device__ __forceinline__ void split3(float x, unsigned short& s1,
                                              unsigned short& s2, unsigned short& s3) {
    __nv_bfloat16 b1 = __float2bfloat16_rn(x);
    float r1 = x - __bfloat162float(b1);
    __nv_bfloat16 b2 = __float2bfloat16_rn(r1);
    float r2 = r1 - __bfloat162float(b2);
    __nv_bfloat16 b3 = __float2bfloat16_rn(r2);
    s1 = __bfloat16_as_ushort(b1); s2 = __bfloat16_as_ushort(b2); s3 = __bfloat16_as_ushort(b3);
}
static __device__ __forceinline__ uint32_t swz(uint32_t o) { return o ^ ((o >> 3) & 0x70); }
static __device__ __forceinline__ void put_split4(char* base, int s_mul, int mt, int nch,
                                                  int c, int rb, int kk, float4 v) {
    uint32_t sw = swz(((uint32_t)(rb >> 3) << 10) + ((uint32_t)(rb & 7) << 7) + ((uint32_t)kk << 1));
    float xs[4] = {v.x, v.y, v.z, v.w};
    unsigned short a[3][4];
    #pragma unroll
    for (int i = 0; i < 4; i++) split3(xs[i], a[0][i], a[1][i], a[2][i]);
    #pragma unroll
    for (int s = 0; s < 3; s++) {
        ushort4 o = make_ushort4(a[s][0], a[s][1], a[s][2], a[s][3]);
        *(ushort4*)(base + ((size_t)(s * s_mul + mt) * nch + c) * 16384 + sw) = o;
    }
}
__device__ __forceinline__ float sigm(float x) { return 1.f / (1.f + expf(-x)); }

// ---------------- prep kernels ----------------------------------------------
__global__ void assemble_splitX_kernel(const float* __restrict__ f_pool,
                                       const float* __restrict__ gt) {
    int idx = blockIdx.x * blockDim.x + threadIdx.x;
    if (idx >= BT * 160) return;
    int r = idx / 160, k0 = (idx - r * 160) * 4;   // r = b*32 + t
    float4 v;
    if (k0 < DEPTH) v = *(const float4*)(f_pool + (size_t)r * DEPTH + k0);
    else {
        int t = r & 31;
        v = (t == 0) ? make_float4(0.f, 0.f, 0.f, 0.f)
                     : *(const float4*)(gt + (size_t)(r - 1) * NCC + (k0 - DEPTH));
    }
    put_split4((char*)g_Xs, 128, r >> 7, 10, k0 >> 6, r & 127, k0 & 63, v);
}

// W, rec: columns permuted n -> n' = r*4 + g  (n = g*512 + r)
__global__ void split_W_kernel(const float* __restrict__ W) {
    int idx = blockIdx.x * blockDim.x + threadIdx.x;
    if (idx >= 160 * 2048) return;
    int kc = idx >> 11, n = idx & 2047, k0 = kc * 4;
    int g = n >> 9, r = n & 511, np = r * 4 + g;
    float4 v;
    v.x = W[(size_t)(k0 + 0) * G4 + n]; v.y = W[(size_t)(k0 + 1) * G4 + n];
    v.z = W[(size_t)(k0 + 2) * G4 + n]; v.w = W[(size_t)(k0 + 3) * G4 + n];
    put_split4((char*)g_Ws, 16, np >> 7, 10, k0 >> 6, np & 127, k0 & 63, v);
}

__global__ void split_rec_kernel(const float* __restrict__ rec) {
    int idx = blockIdx.x * blockDim.x + threadIdx.x;
    if (idx >= 128 * 2048) return;
    int kc = idx >> 11, n = idx & 2047, k0 = kc * 4;
    int g = n >> 9, r = n & 511, np = r * 4 + g;
    float4 v;
    v.x = rec[(size_t)(k0 + 0) * G4 + n]; v.y = rec[(size_t)(k0 + 1) * G4 + n];
    v.z = rec[(size_t)(k0 + 2) * G4 + n]; v.w = rec[(size_t)(k0 + 3) * G4 + n];
    put_split4((char*)g_Rs, 16, np >> 7, 8, k0 >> 6, np & 127, k0 & 63, v);
}

// softmax_w [512 x 128], natural column order
__global__ void split_sw_kernel(const float* __restrict__ sw_) {
    int idx = blockIdx.x * blockDim.x + threadIdx.x;
    if (idx >= 128 * 128) return;
    int kc = idx >> 7, n = idx & 127, k0 = kc * 4;
    float4 v;
    v.x = sw_[(size_t)(k0 + 0) * NCC + n]; v.y = sw_[(size_t)(k0 + 1) * NCC + n];
    v.z = sw_[(size_t)(k0 + 2) * NCC + n]; v.w = sw_[(size_t)(k0 + 3) * NCC + n];
    put_split4((char*)g_Ss, 1, 0, 8, k0 >> 6, n, k0 & 63, v);
}

// ============ 6-product split GEMM via mma.sync bf16 HMMA ===================
// CTA tile 128x128, 8 warps (warp tile 64x32), cp.async double-buffered.
// mode 0: g_Z = X@W + bias   grid(16,128,1), chunks 0..9, A=g_Xs
// mode 1: g_part[kz] = h@rec grid(16,4,2),   chunks kz*4..+3, A=g_hL at amt0
__global__ __launch_bounds__(256) void hmma6_kernel(int mode, int amt0,
                                                    const float* __restrict__ bias_in) {
    extern __shared__ char dsm[];
    const char* A8; const char* B8; int nch; const float* bias; float* out;
    int c0 = 0, c1;
    if (mode == 0) {
        A8 = (const char*)g_Xs; B8 = (const char*)g_Ws;
        nch = 10; bias = bias_in; out = g_Z; c1 = 10;
    } else {
        A8 = (const char*)g_hL; B8 = (const char*)g_Rs;
        nch = 8; bias = nullptr;
        out = g_part + (size_t)blockIdx.z * (Bb * G4);
        c0 = blockIdx.z * 4; c1 = c0 + 4;
    }
    const int tid = threadIdx.x, lane = tid & 31, wid = tid >> 5;
    const int mt = blockIdx.y, nt = blockIdx.x;
    const int wm = wid & 1, wn = wid >> 1;
    uint32_t buf0 = (s2u(dsm) + 1023u) & ~1023u;

    const int l7 = lane & 7;
    const uint32_t xm = (uint32_t)l7 << 4;
    const int asub = lane >> 3;
    const uint32_t akoff = (uint32_t)(asub >> 1) * 16;
    const uint32_t bkoff = (uint32_t)((lane >> 3) & 1) * 16;
    uint32_t arb[4], brb[4];
    #pragma unroll
    for (int m4 = 0; m4 < 4; m4++) {
        int row = wm * 64 + m4 * 16 + (asub & 1) * 8 + l7;
        arb[m4] = (uint32_t)(row >> 3) * 1024u + (uint32_t)l7 * 128u;
    }
    #pragma unroll
    for (int n4 = 0; n4 < 4; n4++) {
        int row = wn * 32 + n4 * 8 + l7;
        brb[n4] = (uint32_t)(row >> 3) * 1024u + (uint32_t)l7 * 128u;
    }

    float acc[4][4][4];
    #pragma unroll
    for (int m4 = 0; m4 < 4; m4++)
        #pragma unroll
        for (int n4 = 0; n4 < 4; n4++)
            #pragma unroll
            for (int e = 0; e < 4; e++) acc[m4][n4][e] = 0.f;

    auto load_chunk = [&](int c, int bb) {
        uint32_t sb = buf0 + (uint32_t)bb * 98304u;
        #pragma unroll
        for (int tau = 0; tau < 6; tau++) {
            const char* g = (tau < 3)
                ? A8 + ((size_t)(tau * 128 + amt0 + mt) * nch + c) * 16384
                : B8 + ((size_t)((tau - 3) * 16 + nt) * nch + c) * 16384;
            uint32_t sdst = sb + (uint32_t)tau * 16384u + (uint32_t)tid * 16u;
            const char* gs = g + tid * 16;
            #pragma unroll
            for (int u = 0; u < 4; u++) cp16(sdst + u * 4096u, gs + u * 4096);
        }
    };

    load_chunk(c0, 0);
    CP_COMMIT();
    for (int c = c0; c < c1; c++) {
        int cur = (c - c0) & 1;
        if (c + 1 < c1) { load_chunk(c + 1, cur ^ 1); CP_COMMIT(); CP_WAIT(1); }
        else CP_WAIT(0);
        __syncthreads();
        uint32_t sb = buf0 + (uint32_t)cur * 98304u;
        #pragma unroll
        for (int ks = 0; ks < 4; ks++) {
            uint32_t kb = (uint32_t)ks * 32;
            uint32_t a[3][4][4];
            #pragma unroll
            for (int s = 0; s < 3; s++) {
                uint32_t ab = sb + (uint32_t)s * 16384u + ((kb + akoff) ^ xm);
                #pragma unroll
                for (int m4 = 0; m4 < 4; m4++) ldsm4(a[s][m4], ab + arb[m4]);
            }
            #pragma unroll
            for (int j = 0; j < 3; j++) {
                uint32_t b[4][2];
                uint32_t bbq = sb + 49152u + (uint32_t)j * 16384u + ((kb + bkoff) ^ xm);
                #pragma unroll
                for (int n4 = 0; n4 < 4; n4++) ldsm2(b[n4], bbq + brb[n4]);
                #pragma unroll
                for (int i = 0; i + j < 3; i++)
                    #pragma unroll
                    for (int m4 = 0; m4 < 4; m4++)
                        #pragma unroll
                        for (int n4 = 0; n4 < 4; n4++)
                            mma16816(acc[m4][n4], a[i][m4], b[n4]);
            }
        }
        __syncthreads();
    }

    #pragma unroll
    for (int m4 = 0; m4 < 4; m4++) {
        int grow = mt * 128 + wm * 64 + m4 * 16 + (lane >> 2);
        #pragma unroll
        for (int n4 = 0; n4 < 4; n4++) {
            int gcol = nt * 128 + wn * 32 + n4 * 8 + (lane & 3) * 2;
            float b0 = 0.f, b1 = 0.f;
            if (bias) {                       // bias permute: n' -> n = (n'&3)*512 + (n'>>2)
                b0 = bias[(gcol & 3) * 512 + (gcol >> 2)];
                b1 = bias[((gcol + 1) & 3) * 512 + ((gcol + 1) >> 2)];
            }
            float2 v;
            v.x = acc[m4][n4][0] + b0; v.y = acc[m4][n4][1] + b1;
            *(float2*)(out + (size_t)grow * G4 + gcol) = v;
            v.x = acc[m4][n4][2] + b0; v.y = acc[m4][n4][3] + b1;
            *(float2*)(out + (size_t)(grow + 8) * G4 + gcol) = v;
        }
    }
}

// ---------------- gate: Z(+parts) + c -> h, c, archive splits ---------------
__global__ __launch_bounds__(256) void gate_kernel(int t, int use_part) {
    int idx = blockIdx.x * blockDim.x + threadIdx.x;
    if (idx >= Bb * 128) return;
    int r4 = (idx & 127) * 4, b = idx >> 7;
    const float* __restrict__ c_prev = (t & 1) ? g_c1 : g_c0;
    float* __restrict__ c_out = (t & 1) ? g_c0 : g_c1;
    float* __restrict__ h_out = g_hall + (size_t)(t + 1) * BRNN;

    const float* zb = g_Z + ((size_t)b * Tt + t) * G4 + r4 * 4;
    const float* p0 = g_part + (size_t)b * G4 + r4 * 4;
    const float* p1 = p0 + (size_t)Bb * G4;
    float4 cp = (t == 0) ? make_float4(0.f, 0.f, 0.f, 0.f)
                         : *(const float4*)(c_prev + (size_t)b * RNN + r4);
    float cpv[4] = {cp.x, cp.y, cp.z, cp.w};
    float4 cv, hv;
    float* cvp = &cv.x; float* hvp = &hv.x;
    #pragma unroll
    for (int u = 0; u < 4; u++) {
        float4 z = *(const float4*)(zb + u * 4);
        if (use_part) {
            float4 p = *(const float4*)(p0 + u * 4);
            float4 q = *(const float4*)(p1 + u * 4);
            z.x += p.x + q.x; z.y += p.y + q.y; z.z += p.z + q.z; z.w += p.w + q.w;
        }
        float c2 = sigm(z.y) * cpv[u] + sigm(z.x) * tanhf(z.z);
        float h2 = sigm(z.w) * tanhf(c2);
        cvp[u] = c2; hvp[u] = h2;
    }
    *(float4*)(c_out + (size_t)b * RNN + r4) = cv;
    *(float4*)(h_out + (size_t)b * RNN + r4) = hv;
    // archive h_{t+1} splits at rows R = t*512 + b  (serves step t+1 AND logits)
    put_split4((char*)g_hL, 128, t * 4 + (b >> 7), 8, r4 >> 6, b & 127, r4 & 63, hv);
}

// ============ logits via HMMA split + fused argmax/one-hot ==================
// grid(128): mtile = R-slab of archive. N=128 (full), K=512, 8 chunks.
__global__ __launch_bounds__(256) void hmma_logits_kernel(
    const float* __restrict__ sb_, float* __restrict__ out) {
    extern __shared__ char dsm[];
    const char* A8 = (const char*)g_hL;
    const char* B8 = (const char*)g_Ss;
    const int tid = threadIdx.x, lane = tid & 31, wid = tid >> 5;
    const int mt = blockIdx.x;
    const int wm = wid & 1, wn = wid >> 1;
    uint32_t buf0 = (s2u(dsm) + 1023u) & ~1023u;

    const int l7 = lane & 7;
    const uint32_t xm = (uint32_t)l7 << 4;
    const int asub = lane >> 3;
    const uint32_t akoff = (uint32_t)(asub >> 1) * 16;
    const uint32_t bkoff = (uint32_t)((lane >> 3) & 1) * 16;
    uint32_t arb[4], brb[4];
    #pragma unroll
    for (int m4 = 0; m4 < 4; m4++) {
        int row = wm * 64 + m4 * 16 + (asub & 1) * 8 + l7;
        arb[m4] = (uint32_t)(row >> 3) * 1024u + (uint32_t)l7 * 128u;
    }
    #pragma unroll
    for (int n4 = 0; n4 < 4; n4++) {
        int row = wn * 32 + n4 * 8 + l7;
        brb[n4] = (uint32_t)(row >> 3) * 1024u + (uint32_t)l7 * 128u;
    }

    float acc[4][4][4];
    #pragma unroll
    for (int m4 = 0; m4 < 4; m4++)
        #pragma unroll
        for (int n4 = 0; n4 < 4; n4++)
            #pragma unroll
            for (int e = 0; e < 4; e++) acc[m4][n4][e] = 0.f;

    auto load_chunk = [&](int c, int bb) {
        uint32_t sb = buf0 + (uint32_t)bb * 98304u;
        #pragma unroll
        for (int tau = 0; tau < 6; tau++) {
            const char* g = (tau < 3)
                ? A8 + ((size_t)(tau * 128 + mt) * 8 + c) * 16384
                : B8 + ((size_t)((tau - 3) * 8 + c)) * 16384;
            uint32_t sdst = sb + (uint32_t)tau * 16384u + (uint32_t)tid * 16u;
            const char* gs = g + tid * 16;
            #pragma unroll
            for (int u = 0; u < 4; u++) cp16(sdst + u * 4096u, gs + u * 4096);
        }
    };

    load_chunk(0, 0);
    CP_COMMIT();
    for (int c = 0; c < 8; c++) {
        int cur = c & 1;
        if (c + 1 < 8) { load_chunk(c + 1, cur ^ 1); CP_COMMIT(); CP_WAIT(1); }
        else CP_WAIT(0);
        __syncthreads();
        uint32_t sb = buf0 + (uint32_t)cur * 98304u;
        #pragma unroll
        for (int ks = 0; ks < 4; ks++) {
            uint32_t kb = (uint32_t)ks * 32;
            uint32_t a[3][4][4];
            #pragma unroll
            for (int s = 0; s < 3; s++) {
                uint32_t ab = sb + (uint32_t)s * 16384u + ((kb + akoff) ^ xm);
                #pragma unroll
                for (int m4 = 0; m4 < 4; m4++) ldsm4(a[s][m4], ab + arb[m4]);
            }
            #pragma unroll
            for (int j = 0; j < 3; j++) {
                uint32_t b[4][2];
                uint32_t bbq = sb + 49152u + (uint32_t)j * 16384u + ((kb + bkoff) ^ xm);
                #pragma unroll
                for (int n4 = 0; n4 < 4; n4++) ldsm2(b[n4], bbq + brb[n4]);
                #pragma unroll
                for (int i = 0; i + j < 3; i++)
                    #pragma unroll
                    for (int m4 = 0; m4 < 4; m4++)
                        #pragma unroll
                        for (int n4 = 0; n4 < 4; n4++)
                            mma16816(acc[m4][n4], a[i][m4], b[n4]);
            }
        }
        __syncthreads();
    }

    // stage logits (+bias) to smem, then block argmax -> one-hot
    float* S = (float*)(size_t)(buf0 - s2u(dsm) + (size_t)dsm);  // reuse buffer region
    {
        float* Sf = (float*)dsm;  // plain view; use padded stride 132
        (void)S;
        #pragma unroll
        for (int m4 = 0; m4 < 4; m4++) {
            int row = wm * 64 + m4 * 16 + (lane >> 2);
            #pragma unroll
            for (int n4 = 0; n4 < 4; n4++) {
                int col = wn * 32 + n4 * 8 + (lane & 3) * 2;
                float b0 = sb_[col], b1 = sb_[col + 1];
                Sf[(size_t)row * 132 + col] = acc[m4][n4][0] + b0;
                Sf[(size_t)row * 132 + col + 1] = acc[m4][n4][1] + b1;
                Sf[(size_t)(row + 8) * 132 + col] = acc[m4][n4][2] + b0;
                Sf[(size_t)(row + 8) * 132 + col + 1] = acc[m4][n4][3] + b1;
            }
        }
    }
    __syncthreads();
    if (tid < 128) {
        const float* rp = (const float*)dsm + (size_t)tid * 132;
        float best = rp[0]; int bidx = 0;
        #pragma unroll 8
        for (int j = 1; j < 128; j++) {
            float v = rp[j];
            if (v > best) { best = v; bidx = j; }
        }
        int R = mt * 128 + tid;          // R = t*512 + b
        int t = R >> 9, b = R & 511;
        float* orow = out + (size_t)b * (Tt * NCC) + t * NCC;
        for (int j4 = 0; j4 < 128; j4 += 4) {
            float4 v;
            v.x = (j4 + 0 == bidx) ? 1.f : 0.f;
            v.y = (j4 + 1 == bidx) ? 1.f : 0.f;
            v.z = (j4 + 2 == bidx) ? 1.f : 0.f;
            v.w = (j4 + 3 == bidx) ? 1.f : 0.f;
            *(float4*)(orow + j4) = v;
        }
    }
}

__global__ void copy_final_kernel(float* __restrict__ out) {
    int i = blockIdx.x * blockDim.x + threadIdx.x;
    if (i < BRNN) {
        out[BT * NCC + i] = g_hall[(size_t)Tt * BRNN + i];
        out[BT * NCC + BRNN + i] = g_c0[i];   // t=31 odd -> wrote g_c0
    }
}

// ---------------- launch -----------------------------------------------------
extern "C" void kernel_launch(void* const* d_in, const int* in_sizes, int n_in,
                              void* d_out, int out_size) {
    const float* f_pool = (const float*)d_in[0];
    const float* gt     = (const float*)d_in[1];
    const float* W      = (const float*)d_in[2];
    const float* rec    = (const float*)d_in[3];
    const float* bias   = (const float*)d_in[4];
    const float* sw_    = (const float*)d_in[5];
    const float* sb_    = (const float*)d_in[6];
    float* out = (float*)d_out;

    static int once = 0;
    if (!once) {
        cudaFuncSetAttribute(hmma6_kernel, cudaFuncAttributeMaxDynamicSharedMemorySize, SMEM_DYN);
        cudaFuncSetAttribute(hmma_logits_kernel, cudaFuncAttributeMaxDynamicSharedMemorySize, SMEM_DYN);
        once = 1;
    }

    assemble_splitX_kernel<<<(BT * 160 + 255) / 256, 256>>>(f_pool, gt);
    split_W_kernel<<<(160 * 2048 + 255) / 256, 256>>>(W);
    split_rec_kernel<<<(128 * 2048 + 255) / 256, 256>>>(rec);
    split_sw_kernel<<<(128 * 128 + 255) / 256, 256>>>(sw_);

    hmma6_kernel<<<dim3(16, 128, 1), 256, SMEM_DYN>>>(0, 0, bias);

    const int gate_blocks = (Bb * 128 + 255) / 256;
    for (int t = 0; t < Tt; t++) {
        if (t > 0)
            hmma6_kernel<<<dim3(16, 4, 2), 256, SMEM_DYN>>>(1, (t - 1) * 4, nullptr);
        gate_kernel<<<gate_blocks, 256>>>(t, t > 0 ? 1 : 0);
    }

    hmma_logits_kernel<<<128, 256, SMEM_DYN>>>(sb_, out);
    copy_final_kernel<<<(BRNN + 255) / 256, 256>>>(out);
}